// round 1
// baseline (speedup 1.0000x reference)
#include <cuda_runtime.h>
#include <math.h>

// Problem constants (fixed by setup_inputs)
#define BATCH 8
#define NQ 200
#define HM 256
#define WM 256
#define NC 81
#define TOPK_N 100
#define SH 192      // scaled_h (crop height)
#define SW 256      // scaled_w (crop width)
#define OH 384      // origin_h
#define OW 512      // origin_w
#define MIN_SCORE 0.1f

// Output packing (float32, concatenated in reference-return order)
#define OFF_MASKS   0UL
#define OFF_SCORES  ((size_t)BATCH * TOPK_N * OH * OW)          // 157286400
#define OFF_CLASSES (OFF_SCORES + (size_t)BATCH * TOPK_N)       // +800
#define OFF_VALID   (OFF_CLASSES + (size_t)BATCH * TOPK_N)      // +800

// Scratch (no cudaMalloc allowed)
__device__ float g_scores[BATCH * NQ];
__device__ int   g_classes[BATCH * NQ];
__device__ int   g_topidx[BATCH * TOPK_N];
__device__ int   g_valid[BATCH * TOPK_N];

// ---------------------------------------------------------------------------
// Kernel 1: per-(b,q) softmax over 81 classes, drop last, max/argmax over 80
// ---------------------------------------------------------------------------
__global__ void classify_kernel(const float* __restrict__ cls)
{
    int t = blockIdx.x * blockDim.x + threadIdx.x;
    if (t >= BATCH * NQ) return;
    const float* p = cls + (size_t)t * NC;

    float m = -1e30f;
    #pragma unroll
    for (int i = 0; i < NC; i++) m = fmaxf(m, p[i]);

    float s = 0.f;
    float best = -1e30f;
    int bi = 0;
    #pragma unroll
    for (int i = 0; i < NC; i++) {
        float v = p[i];
        s += __expf(v - m);
        if (i < NC - 1 && v > best) { best = v; bi = i; }  // first-max tie-break
    }
    g_scores[t]  = __expf(best - m) / s;
    g_classes[t] = bi;
}

// ---------------------------------------------------------------------------
// Kernel 2: per-batch top-100 of 200 by rank-counting (stable, descending),
// writes scores/classes/valid tails of d_out and the gather index table.
// ---------------------------------------------------------------------------
__global__ void topk_kernel(float* __restrict__ out)
{
    __shared__ float s[NQ];
    int b = blockIdx.x;
    for (int q = threadIdx.x; q < NQ; q += blockDim.x)
        s[q] = g_scores[b * NQ + q];
    __syncthreads();

    for (int q = threadIdx.x; q < NQ; q += blockDim.x) {
        float v = s[q];
        int rank = 0;
        for (int j = 0; j < NQ; j++) {
            float u = s[j];
            rank += (u > v) || (u == v && j < q);
        }
        if (rank < TOPK_N) {
            int o   = b * TOPK_N + rank;
            int vld = (v > MIN_SCORE) ? 1 : 0;
            g_topidx[o] = q;
            g_valid[o]  = vld;
            out[OFF_SCORES  + o] = vld ? v : 0.f;
            out[OFF_CLASSES + o] = vld ? (float)g_classes[b * NQ + q] : -1.f;
            out[OFF_VALID   + o] = vld ? 1.f : 0.f;
        }
    }
}

// ---------------------------------------------------------------------------
// Kernel 3: gather selected mask, sigmoid once per input pixel into SMEM,
// separable 2x bilinear (weights 0.75/0.25, clamped edges), float4 stores.
// Output tile: 32 rows x 64 cols. Input tile needed: 18 rows x 34 cols.
// Grid: (8 tilesX, 12 tilesY, 800 masks), 256 threads/block.
// ---------------------------------------------------------------------------
#define TILE_W 64
#define TILE_H 32
#define IN_R 18
#define IN_C 34
#define IN_CP 35   // padded stride

__global__ __launch_bounds__(256)
void resize_kernel(const float* __restrict__ mp, float* __restrict__ out)
{
    const int z = blockIdx.z;                 // b*TOPK + k
    const int C = blockIdx.x * TILE_W;        // output col base
    const int R = blockIdx.y * TILE_H;        // output row base
    const int tid = threadIdx.x;
    const int tx = tid & 15;                  // 16 threads across -> 64 cols via float4
    const int ty = tid >> 4;                  // 16 rows, 2 passes

    float* obase = out + OFF_MASKS + (size_t)z * OH * OW;

    if (!g_valid[z]) {
        const float4 zero = make_float4(0.f, 0.f, 0.f, 0.f);
        #pragma unroll
        for (int half = 0; half < 2; half++) {
            int gy = R + ty + half * 16;
            *reinterpret_cast<float4*>(obase + (size_t)gy * OW + C + 4 * tx) = zero;
        }
        return;
    }

    __shared__ float sm[IN_R * IN_CP];

    const int b   = z / TOPK_N;
    const int sel = g_topidx[z];
    const float* ibase = mp + ((size_t)(b * NQ + sel)) * HM * WM;

    const int Ic = R >> 1;   // input row base
    const int Jc = C >> 1;   // input col base

    // Load input halo tile, apply sigmoid once per input pixel.
    for (int i = tid; i < IN_R * IN_C; i += 256) {
        int r = i / IN_C, c = i - r * IN_C;
        int gr = min(max(Ic - 1 + r, 0), SH - 1);   // clamp within CROPPED region
        int gc = min(max(Jc - 1 + c, 0), SW - 1);
        float x = __ldg(ibase + (size_t)gr * WM + gc);
        sm[r * IN_CP + c] = __fdividef(1.f, 1.f + __expf(-x));
    }
    __syncthreads();

    #pragma unroll
    for (int half = 0; half < 2; half++) {
        int oy = ty + half * 16;
        int gy = R + oy;
        int lr = oy >> 1;
        int r0, r1; float wy0, wy1;
        if (oy & 1) { r0 = lr + 1; r1 = lr + 2; wy0 = 0.75f; wy1 = 0.25f; }
        else        { r0 = lr;     r1 = lr + 1; wy0 = 0.25f; wy1 = 0.75f; }

        int lc = tx * 2;  // smem col base; need cols lc..lc+3
        const float* pa = sm + r0 * IN_CP + lc;
        const float* pb = sm + r1 * IN_CP + lc;
        float v0 = wy0 * pa[0] + wy1 * pb[0];
        float v1 = wy0 * pa[1] + wy1 * pb[1];
        float v2 = wy0 * pa[2] + wy1 * pb[2];
        float v3 = wy0 * pa[3] + wy1 * pb[3];

        float4 o4;
        o4.x = 0.25f * v0 + 0.75f * v1;   // ox even
        o4.y = 0.75f * v1 + 0.25f * v2;   // ox odd
        o4.z = 0.25f * v1 + 0.75f * v2;   // ox+2 even
        o4.w = 0.75f * v2 + 0.25f * v3;   // ox+3 odd
        *reinterpret_cast<float4*>(obase + (size_t)gy * OW + C + 4 * tx) = o4;
    }
}

// ---------------------------------------------------------------------------
extern "C" void kernel_launch(void* const* d_in, const int* in_sizes, int n_in,
                              void* d_out, int out_size)
{
    // metadata order: mask_preds, class_preds, scaled_h, scaled_w, origin_h, origin_w
    const float* mask_preds  = (const float*)d_in[0];
    const float* class_preds = (const float*)d_in[1];
    // defensive: if the first two are swapped, fix by element count
    if (in_sizes[0] == BATCH * NQ * NC) {
        const float* t = mask_preds; mask_preds = class_preds; class_preds = t;
    }
    float* out = (float*)d_out;

    classify_kernel<<<(BATCH * NQ + 255) / 256, 256>>>(class_preds);
    topk_kernel<<<BATCH, 256>>>(out);

    dim3 grid(OW / TILE_W, OH / TILE_H, BATCH * TOPK_N);   // (8, 12, 800)
    resize_kernel<<<grid, 256>>>(mask_preds, out);
}

// round 2
// speedup vs baseline: 1.0950x; 1.0950x over previous
#include <cuda_runtime.h>
#include <math.h>

// Problem constants (fixed by setup_inputs)
#define BATCH 8
#define NQ 200
#define HM 256
#define WM 256
#define NC 81
#define TOPK_N 100
#define SH 192      // scaled_h (crop height)
#define SW 256      // scaled_w (crop width)
#define OH 384      // origin_h
#define OW 512      // origin_w
#define MIN_SCORE 0.1f

// Output packing (float32, concatenated in reference-return order)
#define OFF_MASKS   0UL
#define OFF_SCORES  ((size_t)BATCH * TOPK_N * OH * OW)          // 157286400
#define OFF_CLASSES (OFF_SCORES + (size_t)BATCH * TOPK_N)       // +800
#define OFF_VALID   (OFF_CLASSES + (size_t)BATCH * TOPK_N)      // +800

// Scratch (no cudaMalloc allowed)
__device__ int g_topidx[BATCH * TOPK_N];
__device__ int g_valid[BATCH * TOPK_N];

// ---------------------------------------------------------------------------
// Kernel 1 (fused classify + topk): one block per batch.
// Phase A: warp-per-query softmax/argmax with coalesced loads over 81 classes.
// Phase B: rank-count top-100 of 200 (stable, descending), write tails.
// ---------------------------------------------------------------------------
__global__ __launch_bounds__(256)
void classify_topk_kernel(const float* __restrict__ cls, float* __restrict__ out)
{
    __shared__ float ssc[NQ];
    __shared__ int   scl[NQ];

    const int b    = blockIdx.x;
    const int warp = threadIdx.x >> 5;
    const int lane = threadIdx.x & 31;

    for (int q = warp; q < NQ; q += 8) {
        const float* p = cls + (size_t)(b * NQ + q) * NC;
        // lanes cover indices lane, lane+32, lane+64 (last predicated, 81 total)
        float v0 = p[lane];
        float v1 = p[lane + 32];
        float v2 = (lane < NC - 64) ? p[lane + 64] : -1e30f;   // lanes 0..16

        float m = fmaxf(v0, fmaxf(v1, v2));
        #pragma unroll
        for (int o = 16; o > 0; o >>= 1) m = fmaxf(m, __shfl_xor_sync(0xffffffffu, m, o));

        float s = __expf(v0 - m) + __expf(v1 - m) + ((lane < NC - 64) ? __expf(v2 - m) : 0.f);
        #pragma unroll
        for (int o = 16; o > 0; o >>= 1) s += __shfl_xor_sync(0xffffffffu, s, o);

        // argmax over first 80 classes (exclude idx 80 = lane 16's v2),
        // first-occurrence tie-break (strictly-greater replaces).
        float bv = v0; int bi = lane;
        if (v1 > bv)                { bv = v1; bi = lane + 32; }
        if (lane < 16 && v2 > bv)   { bv = v2; bi = lane + 64; }
        #pragma unroll
        for (int o = 16; o > 0; o >>= 1) {
            float ov = __shfl_xor_sync(0xffffffffu, bv, o);
            int   oi = __shfl_xor_sync(0xffffffffu, bi, o);
            if (ov > bv || (ov == bv && oi < bi)) { bv = ov; bi = oi; }
        }
        if (lane == 0) { ssc[q] = __expf(bv - m) / s; scl[q] = bi; }
    }
    __syncthreads();

    for (int q = threadIdx.x; q < NQ; q += blockDim.x) {
        float v = ssc[q];
        int rank = 0;
        for (int j = 0; j < NQ; j++) {
            float u = ssc[j];
            rank += (u > v) || (u == v && j < q);
        }
        if (rank < TOPK_N) {
            int o   = b * TOPK_N + rank;
            int vld = (v > MIN_SCORE) ? 1 : 0;
            g_topidx[o] = q;
            g_valid[o]  = vld;
            out[OFF_SCORES  + o] = vld ? v : 0.f;
            out[OFF_CLASSES + o] = vld ? (float)scl[q] : -1.f;
            out[OFF_VALID   + o] = vld ? 1.f : 0.f;
        }
    }
}

// ---------------------------------------------------------------------------
// Kernel 2: gather + sigmoid + crop + 2x bilinear upsample, full-width tiles.
// Output tile: 16 rows x 512 cols (full width). Three SMEM stages:
//   1) raw 10x256 input rows, sigmoid applied once per input pixel
//   2) horizontal 2x upsample -> 10x512 (conflict-free stride-1 reads)
//   3) vertical blend via aligned float4 LDS, streaming float4 stores
// Grid: (24 tilesY, 800 masks), 512 threads/block.
// ---------------------------------------------------------------------------
__global__ __launch_bounds__(512)
void resize_kernel(const float* __restrict__ mp, float* __restrict__ out)
{
    const int z   = blockIdx.y;          // b*TOPK + k
    const int R   = blockIdx.x * 16;     // output row base
    const int tid = threadIdx.x;

    float* obase = out + OFF_MASKS + (size_t)z * OH * OW;

    if (!g_valid[z]) {
        const float4 zero = make_float4(0.f, 0.f, 0.f, 0.f);
        #pragma unroll
        for (int it = 0; it < 4; it++) {
            int g = tid + it * 512;                  // 2048 float4 = 16x512 floats
            int y = g >> 7, xq = g & 127;
            __stcs(reinterpret_cast<float4*>(obase + (size_t)(R + y) * OW + 4 * xq), zero);
        }
        return;
    }

    __shared__ float sraw[10 * 256];
    __shared__ float H[10 * 512];

    const int b = z / TOPK_N;
    const float* ibase = mp + (size_t)(b * NQ + g_topidx[z]) * HM * WM;
    const int I0 = (R >> 1) - 1;         // global input row of smem row 0 (pre-clamp)

    // Stage 1: load 10 input rows (clamped), sigmoid once per input pixel.
    #pragma unroll
    for (int it = 0; it < 5; it++) {
        int i = tid + it * 512;
        int r = i >> 8, c = i & 255;
        int gr = min(max(I0 + r, 0), SH - 1);
        float x = __ldg(ibase + (size_t)gr * WM + c);
        sraw[i] = __fdividef(1.f, 1.f + __expf(-x));
    }
    __syncthreads();

    // Stage 2: horizontal 2x upsample (weights 0.25/0.75, clamped edges).
    #pragma unroll
    for (int it = 0; it < 5; it++) {
        int i = tid + it * 512;
        int r = i >> 8, c = i & 255;
        const float* rw = sraw + (r << 8);
        float a  = rw[max(c - 1, 0)];
        float m0 = rw[c];
        float p  = rw[min(c + 1, 255)];
        float2 h;
        h.x = 0.25f * a  + 0.75f * m0;   // output col 2c   (even)
        h.y = 0.75f * m0 + 0.25f * p;    // output col 2c+1 (odd)
        *reinterpret_cast<float2*>(H + r * 512 + 2 * c) = h;
    }
    __syncthreads();

    // Stage 3: vertical blend, aligned float4 loads, streaming float4 stores.
    #pragma unroll
    for (int it = 0; it < 4; it++) {
        int g = tid + it * 512;
        int y = g >> 7, xq = g & 127;
        int iy = y >> 1;
        int r0; float w0, w1;
        if (y & 1) { r0 = iy + 1; w0 = 0.75f; w1 = 0.25f; }
        else       { r0 = iy;     w0 = 0.25f; w1 = 0.75f; }
        float4 va = *reinterpret_cast<const float4*>(H + r0 * 512 + 4 * xq);
        float4 vb = *reinterpret_cast<const float4*>(H + (r0 + 1) * 512 + 4 * xq);
        float4 o;
        o.x = w0 * va.x + w1 * vb.x;
        o.y = w0 * va.y + w1 * vb.y;
        o.z = w0 * va.z + w1 * vb.z;
        o.w = w0 * va.w + w1 * vb.w;
        __stcs(reinterpret_cast<float4*>(obase + (size_t)(R + y) * OW + 4 * xq), o);
    }
}

// ---------------------------------------------------------------------------
extern "C" void kernel_launch(void* const* d_in, const int* in_sizes, int n_in,
                              void* d_out, int out_size)
{
    const float* mask_preds  = (const float*)d_in[0];
    const float* class_preds = (const float*)d_in[1];
    if (in_sizes[0] == BATCH * NQ * NC) {   // defensive swap
        const float* t = mask_preds; mask_preds = class_preds; class_preds = t;
    }
    float* out = (float*)d_out;

    classify_topk_kernel<<<BATCH, 256>>>(class_preds, out);

    dim3 grid(OH / 16, BATCH * TOPK_N);     // (24, 800)
    resize_kernel<<<grid, 512>>>(mask_preds, out);
}

// round 3
// speedup vs baseline: 1.3077x; 1.1943x over previous
#include <cuda_runtime.h>
#include <math.h>
#include <cstdint>

// Problem constants (fixed by setup_inputs)
#define BATCH 8
#define NQ 200
#define HM 256
#define WM 256
#define NC 81
#define TOPK_N 100
#define SH 192      // scaled_h (crop height)  -- crop is rows only, full width
#define SW 256      // scaled_w (crop width == WM)
#define OH 384      // origin_h
#define OW 512      // origin_w
#define MIN_SCORE 0.1f

// Output packing (float32, concatenated in reference-return order)
#define OFF_MASKS   0UL
#define OFF_SCORES  ((size_t)BATCH * TOPK_N * OH * OW)
#define OFF_CLASSES (OFF_SCORES + (size_t)BATCH * TOPK_N)
#define OFF_VALID   (OFF_CLASSES + (size_t)BATCH * TOPK_N)

// Scratch (no cudaMalloc allowed)
__device__ float g_scores[BATCH * NQ];
__device__ int   g_classes[BATCH * NQ];
__device__ int   g_topidx[BATCH * TOPK_N];
__device__ int   g_valid[BATCH * TOPK_N];

__device__ __forceinline__ uint32_t smem_u32(const void* p) {
    uint32_t a;
    asm("{ .reg .u64 t; cvta.to.shared.u64 t, %1; cvt.u32.u64 %0, t; }" : "=r"(a) : "l"(p));
    return a;
}

// ---------------------------------------------------------------------------
// Kernel 1: warp-per-(b,q) softmax/argmax over 81 classes. 200 blocks.
// ---------------------------------------------------------------------------
__global__ __launch_bounds__(256)
void classify_kernel(const float* __restrict__ cls)
{
    const int lane = threadIdx.x & 31;
    const int t = blockIdx.x * 8 + (threadIdx.x >> 5);   // 0..1599
    if (t >= BATCH * NQ) return;

    const float* p = cls + (size_t)t * NC;
    float v0 = p[lane];
    float v1 = p[lane + 32];
    float v2 = (lane < NC - 64) ? p[lane + 64] : -1e30f;

    float m = fmaxf(v0, fmaxf(v1, v2));
    #pragma unroll
    for (int o = 16; o > 0; o >>= 1) m = fmaxf(m, __shfl_xor_sync(0xffffffffu, m, o));

    float s = __expf(v0 - m) + __expf(v1 - m) + ((lane < NC - 64) ? __expf(v2 - m) : 0.f);
    #pragma unroll
    for (int o = 16; o > 0; o >>= 1) s += __shfl_xor_sync(0xffffffffu, s, o);

    // argmax over first 80 classes, first-occurrence tie-break
    float bv = v0; int bi = lane;
    if (v1 > bv)              { bv = v1; bi = lane + 32; }
    if (lane < 16 && v2 > bv) { bv = v2; bi = lane + 64; }
    #pragma unroll
    for (int o = 16; o > 0; o >>= 1) {
        float ov = __shfl_xor_sync(0xffffffffu, bv, o);
        int   oi = __shfl_xor_sync(0xffffffffu, bi, o);
        if (ov > bv || (ov == bv && oi < bi)) { bv = ov; bi = oi; }
    }
    if (lane == 0) { g_scores[t] = __expf(bv - m) / s; g_classes[t] = bi; }
}

// ---------------------------------------------------------------------------
// Kernel 2: per-batch stable top-100 of 200 by rank-counting; writes tails.
// ---------------------------------------------------------------------------
__global__ __launch_bounds__(256)
void topk_kernel(float* __restrict__ out)
{
    __shared__ float s[NQ];
    const int b = blockIdx.x;
    for (int q = threadIdx.x; q < NQ; q += blockDim.x)
        s[q] = g_scores[b * NQ + q];
    __syncthreads();

    for (int q = threadIdx.x; q < NQ; q += blockDim.x) {
        float v = s[q];
        int rank = 0;
        for (int j = 0; j < NQ; j++) {
            float u = s[j];
            rank += (u > v) || (u == v && j < q);
        }
        if (rank < TOPK_N) {
            int o   = b * TOPK_N + rank;
            int vld = (v > MIN_SCORE) ? 1 : 0;
            g_topidx[o] = q;
            g_valid[o]  = vld;
            out[OFF_SCORES  + o] = vld ? v : 0.f;
            out[OFF_CLASSES + o] = vld ? (float)g_classes[b * NQ + q] : -1.f;
            out[OFF_VALID   + o] = vld ? 1.f : 0.f;
        }
    }
}

// ---------------------------------------------------------------------------
// Kernel 3: gather + sigmoid + crop + 2x bilinear upsample.
// Block = 16 output rows x 512 cols of one mask = contiguous 32KB -> TMA bulk
// store. 256 threads. One sigmoid'd input stage in SMEM (10 rows x 256), then
// a register row-walk blend: out rows 2I-1 and 2I both use (h(I-1), h(I)).
// Grid: (24, 800).
// ---------------------------------------------------------------------------
__global__ __launch_bounds__(256)
void resize_kernel(const float* __restrict__ mp, float* __restrict__ out)
{
    __shared__ float ssig[10 * 256];    // 10 KB
    __shared__ float sout[16 * 512];    // 32 KB

    const int z   = blockIdx.y;
    const int R   = blockIdx.x * 16;
    const int tid = threadIdx.x;
    const int valid = g_valid[z];

    float* gdst = out + OFF_MASKS + (size_t)z * (OH * OW) + (size_t)R * OW;

    if (valid) {
        const int b = z / TOPK_N;
        const float4* ibase4 = reinterpret_cast<const float4*>(
            mp + (size_t)(b * NQ + g_topidx[z]) * (HM * WM));
        const int I0 = (R >> 1) - 1;     // global input row of ssig row 0

        // Stage 1: load 10 clamped rows (float4 coalesced), sigmoid once.
        for (int i = tid; i < 640; i += 256) {
            int r  = i >> 6;
            int c4 = i & 63;
            int gr = min(max(I0 + r, 0), SH - 1);
            float4 v = __ldg(ibase4 + gr * 64 + c4);
            float4 sg;
            sg.x = __fdividef(1.f, 1.f + __expf(-v.x));
            sg.y = __fdividef(1.f, 1.f + __expf(-v.y));
            sg.z = __fdividef(1.f, 1.f + __expf(-v.z));
            sg.w = __fdividef(1.f, 1.f + __expf(-v.w));
            *reinterpret_cast<float4*>(ssig + r * 256 + 4 * c4) = sg;
        }
        __syncthreads();

        // Stage 2: register row-walk blend. Thread owns out cols 4g..4g+3.
        const int g    = tid & 127;
        const int half = tid >> 7;
        const int r0   = half * 4;       // ssig row walk start
        const int cm1  = max(2 * g - 1, 0);
        const int c0   = 2 * g;
        const int c1   = 2 * g + 1;
        const int cp2  = min(2 * g + 2, 255);

        float hp0, hp1, hp2, hp3;
        #pragma unroll
        for (int s = 0; s < 6; s++) {
            const float* row = ssig + (r0 + s) * 256;
            float x0 = row[cm1], x1 = row[c0], x2 = row[c1], x3 = row[cp2];
            float h0 = 0.25f * x0 + 0.75f * x1;
            float h1 = 0.75f * x1 + 0.25f * x2;
            float h2 = 0.25f * x1 + 0.75f * x2;
            float h3 = 0.75f * x2 + 0.25f * x3;
            if (s > 0) {
                int oyA = 2 * (r0 + s) - 3;   // odd row: 0.75*hprev + 0.25*hcur
                int oyB = oyA + 1;            // even row: 0.25*hprev + 0.75*hcur
                if (s != 1) {
                    float4 a;
                    a.x = 0.75f * hp0 + 0.25f * h0;
                    a.y = 0.75f * hp1 + 0.25f * h1;
                    a.z = 0.75f * hp2 + 0.25f * h2;
                    a.w = 0.75f * hp3 + 0.25f * h3;
                    *reinterpret_cast<float4*>(sout + oyA * 512 + 4 * g) = a;
                }
                if (s != 5) {
                    float4 e;
                    e.x = 0.25f * hp0 + 0.75f * h0;
                    e.y = 0.25f * hp1 + 0.75f * h1;
                    e.z = 0.25f * hp2 + 0.75f * h2;
                    e.w = 0.25f * hp3 + 0.75f * h3;
                    *reinterpret_cast<float4*>(sout + oyB * 512 + 4 * g) = e;
                }
            }
            hp0 = h0; hp1 = h1; hp2 = h2; hp3 = h3;
        }
    } else {
        // Invalid mask: zero-fill sout.
        const float4 zero = make_float4(0.f, 0.f, 0.f, 0.f);
        #pragma unroll
        for (int it = 0; it < 8; it++)
            *reinterpret_cast<float4*>(sout + 4 * (tid + it * 256)) = zero;
    }
    __syncthreads();

    // Stage 3: single TMA bulk store of the contiguous 32KB tile.
    if (tid == 0) {
        asm volatile("fence.proxy.async.shared::cta;" ::: "memory");
        uint32_t src = smem_u32(sout);
        asm volatile(
            "cp.async.bulk.global.shared::cta.bulk_group [%0], [%1], %2;"
            :: "l"(gdst), "r"(src), "r"(16 * 512 * 4) : "memory");
        asm volatile("cp.async.bulk.commit_group;" ::: "memory");
        asm volatile("cp.async.bulk.wait_group 0;" ::: "memory");
    }
    __syncthreads();   // smem must stay live until the bulk store drains
}

// ---------------------------------------------------------------------------
extern "C" void kernel_launch(void* const* d_in, const int* in_sizes, int n_in,
                              void* d_out, int out_size)
{
    const float* mask_preds  = (const float*)d_in[0];
    const float* class_preds = (const float*)d_in[1];
    if (in_sizes[0] == BATCH * NQ * NC) {   // defensive swap
        const float* t = mask_preds; mask_preds = class_preds; class_preds = t;
    }
    float* out = (float*)d_out;

    classify_kernel<<<200, 256>>>(class_preds);
    topk_kernel<<<BATCH, 256>>>(out);

    dim3 grid(OH / 16, BATCH * TOPK_N);     // (24, 800)
    resize_kernel<<<grid, 256>>>(mask_preds, out);
}